// round 10
// baseline (speedup 1.0000x reference)
#include <cuda_runtime.h>
#include <math_constants.h>

// queries/keys/values: 8192 fp32 each; 8 segments of 1024 contiguous floats.
// dists[i][j] = exact DTW(|a-b|) between q-seg i and k-seg j (1024x1024 DP).
// A = softmax(0.5*dists, axis=-1); out = A @ value-segments.
//
// TWO CTAs per (qi,kj) pair: half h owns columns [512h, 512h+512), each of
// 128 threads owns C=4 columns. Pipeline skew sigma = 184*h + t + 8*warp.
// Cross-CTA seam: CTA0 thread 127 STGs its per-step 4-value right boundary
// into a 1024-slot global ring (written once per launch -> no wrap, no
// overwrite hazard). CTA1 warp 0 prefetches slots 3-4 supersteps early
// (slack = 32 steps) and republishes them into the local smem ring's row 3
// (the INF row) at superstep boundaries, so per-step code is unchanged.
// Flow control: monotone per-pair flag, st.release.gpu by producer per
// superstep; consumer holds a 1-superstep-stale acquire copy and spins only
// if producer >2 supersteps behind (never in steady state; always resident).

#define N_SEG    8
#define SEG_LEN  1024
#define C_COLS   4
#define R_ROWS   4
#define P_THR    128
#define N_BLK    (SEG_LEN / R_ROWS)          // 256
#define SKEW_W   8
#define CROSS_D  32                          // cross-CTA read distance (steps)
#define CTA_OFF  (152 + CROSS_D)             // 184: CTA1 base skew
#define SIG_MAX  (CTA_OFF + 127 + SKEW_W*3)  // 335
#define N_STEPS  (N_BLK + SIG_MAX)           // 591
#define SUPER    8
#define NSUPER   ((N_STEPS + SUPER - 1) / SUPER)   // 74 -> 592 executed steps
#define RING     64
#define N_CTA    (N_SEG * N_SEG * 2)         // 128

__device__ float        g_dists[N_SEG * N_SEG];
__device__ unsigned int g_count = 0;         // self-resetting via atomicInc wrap
__device__ unsigned int g_flag[N_SEG * N_SEG];        // reset by last CTA
__device__ float4       g_xring[N_SEG * N_SEG][1024]; // cross-CTA boundary ring

__device__ __forceinline__ unsigned ld_acq(const unsigned* p) {
    unsigned v;
    asm volatile("ld.acquire.gpu.global.u32 %0, [%1];" : "=r"(v) : "l"(p) : "memory");
    return v;
}
__device__ __forceinline__ void st_rel(unsigned* p, unsigned v) {
    asm volatile("st.release.gpu.global.u32 [%0], %1;" :: "l"(p), "r"(v) : "memory");
}

__global__ __launch_bounds__(P_THR, 1)
void dtw_kernel(const float* __restrict__ q, const float* __restrict__ k,
                const float* __restrict__ values, float* __restrict__ out_g) {
    const int qi   = blockIdx.x;
    const int kj   = blockIdx.y;
    const int half = blockIdx.z;
    const int pair = qi * N_SEG + kj;
    const float* __restrict__ xrow = q + qi * SEG_LEN;
    const float* __restrict__ ycol = k + kj * SEG_LEN;

    __shared__ float  sx[SEG_LEN];
    __shared__ float4 ring[4][RING];         // row 3: INF row / cross-seam row
    __shared__ float  sA[N_SEG][N_SEG];
    __shared__ unsigned s_last;

    const int t    = threadIdx.x;
    const int lane = t & 31;
    const int warp = t >> 5;
    const int tg   = half * P_THR + t;       // global thread 0..255
    const int sigma = half * CTA_OFF + t + SKEW_W * warp;
    const int rdrow = (warp + 3) & 3;        // warp-1; warp0 -> 3
    const float INF = CUDART_INF_F;

    const bool prod = (half == 0) && (t == P_THR - 1);   // cross-seam producer
    const bool cw0  = (half == 1) && (warp == 0);        // cross-seam consumer warp
    const bool seam = (lane == 31) && (warp < 3);        // intra-CTA seam producer

    for (int i = t; i < SEG_LEN / 4; i += P_THR)
        reinterpret_cast<float4*>(sx)[i] = reinterpret_cast<const float4*>(xrow)[i];
    {
        const float4 inf4 = make_float4(INF, INF, INF, INF);
        float4* rp = &ring[0][0];
        for (int i = t; i < 4 * RING; i += P_THR) rp[i] = inf4;
    }

    float y[C_COLS];
    {
        const float4 a = reinterpret_cast<const float4*>(ycol)[tg];  // cols 4*tg..+4
        y[0]=a.x; y[1]=a.y; y[2]=a.z; y[3]=a.w;
    }

    float U[C_COLS];                         // d[r0-1, base+j]
#pragma unroll
    for (int j = 0; j < C_COLS; j++) U[j] = INF;
    float lv0 = INF, lv1 = INF, lv2 = INF, lv3 = INF;
    float carry = (tg == 0) ? 0.0f : INF;
    float res = 0.0f;

    // consumer prefetch state
    float4 nxt[SUPER];
#pragma unroll
    for (int u = 0; u < SUPER; u++) nxt[u] = make_float4(INF, INF, INF, INF);
    unsigned flag_reg = 0;
    const unsigned* flag_p = &g_flag[pair];
    const float4* xr_g = &g_xring[pair][0];
    float4* xr_gw = &g_xring[pair][0];

    __syncthreads();

    const float4* sx4 = reinterpret_cast<const float4*>(sx);

    for (int sup = 0; sup < NSUPER; sup++) {
        // ---- cross-seam consumer boundary (CTA1 warp 0 only) ----
        if (cw0) {
            if (lane == 0) {
                // publish prefetched values for THIS superstep's per-step reads:
                // step s reads ring[3][(s-8)&63]; s = 8*sup+u -> slot (8*sup-8+u)&63
#pragma unroll
                for (int u = 0; u < SUPER; u++)
                    ring[3][(sup * SUPER - SUPER + u) & (RING - 1)] = nxt[u];
                // prefetch for superstep sup+1: gslots 8*(sup+1)-32 + u
                const int g0 = (sup + 1) * SUPER - CROSS_D;
                if (g0 >= 0) {
                    const unsigned need = (unsigned)(sup + 1 - 3); // flag >= nb-3
                    if (flag_reg < need) {
                        do { flag_reg = ld_acq(flag_p); } while (flag_reg < need);
                    }
#pragma unroll
                    for (int u = 0; u < SUPER; u++)
                        nxt[u] = __ldcg(&xr_g[g0 + u]);
                }
                flag_reg = ld_acq(flag_p);   // refresh (latency hidden to next boundary)
            }
            __syncwarp(0xffffffffu);
        }

        const int b0 = sup * SUPER - sigma;
        float4 X[SUPER];
#pragma unroll
        for (int u = 0; u < SUPER; u++) {
            const int iu = min(max(b0 + u, 0), N_BLK - 1);
            X[u] = sx4[iu];
        }

#pragma unroll
        for (int u = 0; u < SUPER; u++) {
            const int s = sup * SUPER + u;
            const int b = b0 + u;
            const float4 xv = X[u];

            // seam consumer pre-load (off-spine)
            const float4 rv = ring[rdrow][(s - SKEW_W) & (RING - 1)];

            // ---- 4x4 tile, column-major ----
            float pc0 = lv0, pc1 = lv1, pc2 = lv2, pc3 = lv3;
            float uleft = carry;
#pragma unroll
            for (int j = 0; j < C_COLS; j++) {
                const float Uj = U[j];
                const float c0 = fabsf(xv.x - y[j]) + fminf(fminf(Uj,  uleft), pc0);
                const float c1 = fabsf(xv.y - y[j]) + fminf(fminf(pc1, pc0), c0);
                const float c2 = fabsf(xv.z - y[j]) + fminf(fminf(pc2, pc1), c1);
                const float c3 = fabsf(xv.w - y[j]) + fminf(fminf(pc3, pc2), c2);
                U[j]  = c3;
                uleft = Uj;
                pc0 = c0; pc1 = c1; pc2 = c2; pc3 = c3;
            }

            res   = (b == N_BLK - 1) ? pc3 : res;
            carry = lv3;

            const float n0 = __shfl_up_sync(0xffffffffu, pc0, 1);
            const float n1 = __shfl_up_sync(0xffffffffu, pc1, 1);
            const float n2 = __shfl_up_sync(0xffffffffu, pc2, 1);
            const float n3 = __shfl_up_sync(0xffffffffu, pc3, 1);

            if (seam)                        // intra-CTA seam: predicated STS.128
                ring[warp][s & (RING - 1)] = make_float4(pc0, pc1, pc2, pc3);
            if (prod)                        // cross-CTA seam: predicated STG.128
                xr_gw[s] = make_float4(pc0, pc1, pc2, pc3);

            const bool l0 = (lane == 0);
            lv0 = l0 ? rv.x : n0;
            lv1 = l0 ? rv.y : n1;
            lv2 = l0 ? rv.z : n2;
            lv3 = l0 ? rv.w : n3;
        }

        if (prod) st_rel((unsigned*)flag_p, (unsigned)(sup + 1));
        __syncthreads();
    }

    if (tg == 2 * P_THR - 1) g_dists[pair] = res;    // d[1023,1023]

    // ---- fused epilogue: last CTA of all 128 does softmax + A @ V ----
    __threadfence();
    if (t == 0) s_last = atomicInc(&g_count, N_CTA - 1);
    __syncthreads();
    if (s_last != N_CTA - 1) return;
    __threadfence();

    // reset cross-seam flags for the next (graph-replayed) launch
    if (t < N_SEG * N_SEG) g_flag[t] = 0;
    __threadfence();

    if (t < N_SEG) {
        float l[N_SEG];
        float m = -INF;
#pragma unroll
        for (int j = 0; j < N_SEG; j++) {
            l[j] = 0.5f * g_dists[t * N_SEG + j];    // scale = 1/sqrt(4)
            m = fmaxf(m, l[j]);
        }
        float ssum = 0.0f;
#pragma unroll
        for (int j = 0; j < N_SEG; j++) {
            l[j] = expf(l[j] - m);
            ssum += l[j];
        }
        const float inv = 1.0f / ssum;
#pragma unroll
        for (int j = 0; j < N_SEG; j++) sA[t][j] = l[j] * inv;
    }
    __syncthreads();

    const float4* v4 = reinterpret_cast<const float4*>(values);
    float4* o4 = reinterpret_cast<float4*>(out_g);
#pragma unroll
    for (int n = 0; n < 16; n++) {
        const int g = t + n * P_THR;                 // float4 index (2048 total)
        const int i = g >> 8;                        // segment (256 float4/seg)
        const int c = g & 255;
        float4 acc = make_float4(0.f, 0.f, 0.f, 0.f);
#pragma unroll
        for (int j = 0; j < N_SEG; j++) {
            const float w = sA[i][j];
            const float4 v = v4[j * 256 + c];
            acc.x += w * v.x;
            acc.y += w * v.y;
            acc.z += w * v.z;
            acc.w += w * v.w;
        }
        o4[g] = acc;
    }
}

extern "C" void kernel_launch(void* const* d_in, const int* in_sizes, int n_in,
                              void* d_out, int out_size) {
    const float* queries = (const float*)d_in[0];
    const float* keys    = (const float*)d_in[1];
    const float* values  = (const float*)d_in[2];
    float* out = (float*)d_out;

    dim3 grid(N_SEG, N_SEG, 2);
    dtw_kernel<<<grid, P_THR>>>(queries, keys, values, out);
}

// round 11
// speedup vs baseline: 2.0511x; 2.0511x over previous
#include <cuda_runtime.h>
#include <math_constants.h>

// queries/keys/values: 8192 fp32 each; 8 segments of 1024 contiguous floats.
// dists[i][j] = exact DTW(|a-b|) between q-seg i and k-seg j (1024x1024 DP).
// A = softmax(0.5*dists, axis=-1); out = A @ value-segments.

#define N_SEG    8
#define SEG_LEN  1024
#define C_COLS   8                            // columns per thread
#define R_ROWS   4                            // rows per pipeline step
#define P_THR    128
#define N_BLK    (SEG_LEN / R_ROWS)           // 256 row-blocks
#define SKEW_W   8                            // extra skew per warp seam
#define SIG_MAX  (P_THR - 1 + SKEW_W * 3)     // 151
#define N_STEPS  (N_BLK + SIG_MAX)            // 407
#define SUPER    8                            // steps per __syncthreads
#define NSUPER   ((N_STEPS + SUPER - 1) / SUPER)   // 51 -> 408 executed steps
#define RING     16

__device__ float        g_dists[N_SEG * N_SEG];
__device__ unsigned int g_count = 0;          // self-resetting via atomicInc wrap

// One CTA per (qi,kj). Fully branch-free pipelined 4x8 register-tile DTW.
// Thread t owns cols [8t,8t+8); skew sigma = t + 8*warp; step s -> block
// b = s - sigma. INF is a fixed point of the recurrence, so out-of-window
// threads run the same code on INF state and produce exactly the correct
// virtual boundaries (x reads wrap-indexed; garbage x only meets INF state
// or post-drain threads).
//   - barrier every SUPER=8 steps (SKEW_W=8 seam slack); ring slot s-8 is
//     always written in the previous superstep; within a superstep, writes
//     cover slots [8k,8k+8) mod 16 and reads [8k-8,8k) mod 16 -> disjoint.
//   - seam consumer: ALL lanes broadcast-load ring[(warp-1)&3][s-8] before
//     the tile, then SEL per element for lane 0 (ring row 3 = permanent INF
//     row for warp 0). Seam producer: one predicated STS.128.
//   - X tiles for superstep sup+1 are loaded BEFORE the barrier (sx is
//     immutable after init; ptxas can't hoist loads across BAR, so we do it
//     in source) -> no superstep-head LDS exposure.
//   - x index wraps with &(N_BLK-1) instead of clamping (saves 2 instr/load).
__global__ __launch_bounds__(P_THR, 1)
void dtw_kernel(const float* __restrict__ q, const float* __restrict__ k,
                const float* __restrict__ values, float* __restrict__ out_g) {
    const int qi = blockIdx.x;
    const int kj = blockIdx.y;
    const float* __restrict__ xrow = q + qi * SEG_LEN;
    const float* __restrict__ ycol = k + kj * SEG_LEN;

    __shared__ float  sx[SEG_LEN];
    __shared__ float4 ring[4][RING];          // row 3: permanent INF row
    __shared__ float  sA[N_SEG][N_SEG];
    __shared__ unsigned s_last;

    const int t    = threadIdx.x;
    const int lane = t & 31;
    const int warp = t >> 5;
    const int sigma = t + SKEW_W * warp;
    const int rdrow = (warp + 3) & 3;         // warp-1; warp0 -> 3 (INF row)
    const float INF = CUDART_INF_F;

    for (int i = t; i < SEG_LEN / 4; i += P_THR)
        reinterpret_cast<float4*>(sx)[i] = reinterpret_cast<const float4*>(xrow)[i];
    {
        const float4 inf4 = make_float4(INF, INF, INF, INF);
        float4* rp = &ring[0][0];
        for (int i = t; i < 4 * RING; i += P_THR) rp[i] = inf4;
    }

    float y[C_COLS];
    {
        const float4* y4 = reinterpret_cast<const float4*>(ycol + t * C_COLS);
        float4 a = y4[0], b = y4[1];
        y[0]=a.x; y[1]=a.y; y[2]=a.z; y[3]=a.w;
        y[4]=b.x; y[5]=b.y; y[6]=b.z; y[7]=b.w;
    }

    float U[C_COLS];                  // d[r0-1, base+j] (top boundary, rolling)
#pragma unroll
    for (int j = 0; j < C_COLS; j++) U[j] = INF;
    float lv0 = INF, lv1 = INF, lv2 = INF, lv3 = INF;   // left boundary
    float carry = (t == 0) ? 0.0f : INF;  // d[r0-1, base-1] entering a block
    float res = 0.0f;

    __syncthreads();

    const float4* sx4 = reinterpret_cast<const float4*>(sx);

    // Prologue: X tiles for superstep 0 (wrap-indexed; garbage is harmless).
    float4 X[SUPER];
#pragma unroll
    for (int u = 0; u < SUPER; u++)
        X[u] = sx4[(0 * SUPER - sigma + u) & (N_BLK - 1)];

    for (int sup = 0; sup < NSUPER; sup++) {
        const int b0 = sup * SUPER - sigma;

#pragma unroll
        for (int u = 0; u < SUPER; u++) {
            const int s = sup * SUPER + u;
            const int b = b0 + u;
            const float4 xv = X[u];

            // seam consumer pre-load (independent of the tile; latency buried)
            const float4 rv = ring[rdrow][(s - SKEW_W) & (RING - 1)];

            // ---- 4x8 tile, column-major ----
            float pc0 = lv0, pc1 = lv1, pc2 = lv2, pc3 = lv3;
            float uleft = carry;              // old U[j-1]
#pragma unroll
            for (int j = 0; j < C_COLS; j++) {
                const float Uj = U[j];
                const float c0 = fabsf(xv.x - y[j]) + fminf(fminf(Uj,  uleft), pc0);
                const float c1 = fabsf(xv.y - y[j]) + fminf(fminf(pc1, pc0), c0);
                const float c2 = fabsf(xv.z - y[j]) + fminf(fminf(pc2, pc1), c1);
                const float c3 = fabsf(xv.w - y[j]) + fminf(fminf(pc3, pc2), c2);
                U[j]  = c3;                   // new top boundary for next block
                uleft = Uj;
                pc0 = c0; pc1 = c1; pc2 = c2; pc3 = c3;
            }
            // pc0..pc3 = right boundary of this block

            res   = (b == N_BLK - 1) ? pc3 : res;    // d[1023, base+7]
            carry = lv3;

            // intra-warp handoff for next step
            const float n0 = __shfl_up_sync(0xffffffffu, pc0, 1);
            const float n1 = __shfl_up_sync(0xffffffffu, pc1, 1);
            const float n2 = __shfl_up_sync(0xffffffffu, pc2, 1);
            const float n3 = __shfl_up_sync(0xffffffffu, pc3, 1);

            // seam producer: single predicated wide store
            if (lane == 31 && warp < 3)
                ring[warp][s & (RING - 1)] = make_float4(pc0, pc1, pc2, pc3);

            // seam consumer select (no branch)
            const bool l0 = (lane == 0);
            lv0 = l0 ? rv.x : n0;
            lv1 = l0 ? rv.y : n1;
            lv2 = l0 ? rv.z : n2;
            lv3 = l0 ? rv.w : n3;
        }

        // Software-pipelined X reload for superstep sup+1, BEFORE the barrier
        // (sx is read-only after init, so this is ordering-safe; it also fills
        // the pre-barrier slack and removes the post-barrier LDS exposure).
        {
            const int b0n = (sup + 1) * SUPER - sigma;
#pragma unroll
            for (int u = 0; u < SUPER; u++)
                X[u] = sx4[(b0n + u) & (N_BLK - 1)];
        }
        __syncthreads();
    }

    if (t == P_THR - 1) g_dists[qi * N_SEG + kj] = res;

    // ---- fused epilogue: last CTA to arrive does softmax + A @ V ----
    __threadfence();
    if (t == 0) s_last = atomicInc(&g_count, N_SEG * N_SEG - 1);
    __syncthreads();
    if (s_last != N_SEG * N_SEG - 1) return;
    __threadfence();

    if (t < N_SEG) {
        float l[N_SEG];
        float m = -INF;
#pragma unroll
        for (int j = 0; j < N_SEG; j++) {
            l[j] = 0.5f * g_dists[t * N_SEG + j];    // scale = 1/sqrt(4)
            m = fmaxf(m, l[j]);
        }
        float ssum = 0.0f;
#pragma unroll
        for (int j = 0; j < N_SEG; j++) {
            l[j] = expf(l[j] - m);
            ssum += l[j];
        }
        const float inv = 1.0f / ssum;
#pragma unroll
        for (int j = 0; j < N_SEG; j++) sA[t][j] = l[j] * inv;
    }
    __syncthreads();

    const float4* v4 = reinterpret_cast<const float4*>(values);
    float4* o4 = reinterpret_cast<float4*>(out_g);
#pragma unroll
    for (int n = 0; n < 16; n++) {
        const int g = t + n * P_THR;                 // float4 index (2048 total)
        const int i = g >> 8;                        // segment (256 float4/seg)
        const int c = g & 255;
        float4 acc = make_float4(0.f, 0.f, 0.f, 0.f);
#pragma unroll
        for (int j = 0; j < N_SEG; j++) {
            const float w = sA[i][j];
            const float4 v = v4[j * 256 + c];
            acc.x += w * v.x;
            acc.y += w * v.y;
            acc.z += w * v.z;
            acc.w += w * v.w;
        }
        o4[g] = acc;
    }
}

extern "C" void kernel_launch(void* const* d_in, const int* in_sizes, int n_in,
                              void* d_out, int out_size) {
    const float* queries = (const float*)d_in[0];
    const float* keys    = (const float*)d_in[1];
    const float* values  = (const float*)d_in[2];
    float* out = (float*)d_out;

    dim3 grid(N_SEG, N_SEG);
    dtw_kernel<<<grid, P_THR>>>(queries, keys, values, out);
}

// round 13
// speedup vs baseline: 2.5091x; 1.2233x over previous
#include <cuda_runtime.h>
#include <math_constants.h>

// queries/keys/values: 8192 fp32 each; 8 segments of 1024 contiguous floats.
// dists[i][j] = exact DTW(|a-b|) between q-seg i and k-seg j (1024x1024 DP).
// A = softmax(0.5*dists, axis=-1); out = A @ value-segments.
//
// BIDIRECTIONAL SPLIT: every monotone DTW path crosses row 511 -> 512 on one
// down/diag edge, so D = min_j [ F[j] + min(B[j], B[j+1]) ] with
// F[j] = Dfwd(511,j) (cost-inclusive) and B[j] = Dbwd(512,j) (cost-inclusive).
// CTA (qi,kj,0) computes F via forward DTW on rows 0..511; CTA (qi,kj,1)
// computes B by running the SAME forward kernel on reversed x rows and
// reversed y cols (Dbwd(i,j) = Dfwd_rev(1023-i,1023-j)), storing its final
// row index-reversed. Whichever partner arrives second (per-pair atomicInc,
// no spinning) does the 1024-wide combine min-reduction.

#define N_SEG    8
#define SEG_LEN  1024
#define HALF_R   512                          // rows per direction
#define C_COLS   8                            // columns per thread
#define R_ROWS   4                            // rows per pipeline step
#define P_THR    128
#define N_BLK    (HALF_R / R_ROWS)            // 128 row-blocks
#define SKEW_W   8                            // extra skew per warp seam
#define SIG_MAX  (P_THR - 1 + SKEW_W * 3)     // 151
#define N_STEPS  (N_BLK + SIG_MAX)            // 279
#define SUPER    8                            // steps per __syncthreads
#define NSUPER   ((N_STEPS + SUPER - 1) / SUPER)   // 35 -> 280 executed steps
#define RING     16
#define N_CTA    (N_SEG * N_SEG * 2)          // 128

__device__ float        g_dists[N_SEG * N_SEG];
__device__ unsigned int g_count = 0;                  // wraps -> self-reset
__device__ unsigned int g_pcount[N_SEG * N_SEG];      // per-pair, wraps at 1
__device__ float        g_F[N_SEG * N_SEG][SEG_LEN];  // Dfwd(511, j)
__device__ float        g_B[N_SEG * N_SEG][SEG_LEN];  // Dbwd(512, j)

__global__ __launch_bounds__(P_THR, 1)
void dtw_kernel(const float* __restrict__ q, const float* __restrict__ k,
                const float* __restrict__ values, float* __restrict__ out_g) {
    const int qi   = blockIdx.x;
    const int kj   = blockIdx.y;
    const int half = blockIdx.z;              // 0 = forward, 1 = backward
    const int pair = qi * N_SEG + kj;
    const float* __restrict__ xrow = q + qi * SEG_LEN;
    const float* __restrict__ ycol = k + kj * SEG_LEN;

    __shared__ float  sx[HALF_R];
    __shared__ float4 ring[4][RING];          // row 3: permanent INF row
    __shared__ float4 sF4[2 * P_THR];         // captured boundary row (1024 f)
    __shared__ float  sA[N_SEG][N_SEG];
    __shared__ float  sRed[4];
    __shared__ unsigned s_sec, s_last;

    const int t    = threadIdx.x;
    const int lane = t & 31;
    const int warp = t >> 5;
    const int sigma = t + SKEW_W * warp;
    const int rdrow = (warp + 3) & 3;         // warp-1; warp0 -> 3 (INF row)
    const float INF = CUDART_INF_F;

    // x rows for this direction (bwd: reversed rows 1023..512)
    {
        const float4* xr4 = reinterpret_cast<const float4*>(xrow);
        float4* sxd = reinterpret_cast<float4*>(sx);
        if (half == 0) {
            sxd[t] = xr4[t];                          // rows 0..511
        } else {
            const float4 v = xr4[255 - t];            // rows 1023..512 reversed
            sxd[t] = make_float4(v.w, v.z, v.y, v.x);
        }
    }
    {
        const float4 inf4 = make_float4(INF, INF, INF, INF);
        float4* rp = &ring[0][0];
        for (int i = t; i < 4 * RING; i += P_THR) rp[i] = inf4;
    }

    // y columns (bwd: reversed)
    float y[C_COLS];
    {
        const float4* kc4 = reinterpret_cast<const float4*>(ycol);
        if (half == 0) {
            const float4 a = kc4[2 * t], b = kc4[2 * t + 1];
            y[0]=a.x; y[1]=a.y; y[2]=a.z; y[3]=a.w;
            y[4]=b.x; y[5]=b.y; y[6]=b.z; y[7]=b.w;
        } else {
            const float4 a = kc4[255 - 2 * t], b = kc4[254 - 2 * t];
            y[0]=a.w; y[1]=a.z; y[2]=a.y; y[3]=a.x;
            y[4]=b.w; y[5]=b.z; y[6]=b.y; y[7]=b.x;
        }
    }

    float U[C_COLS];                  // d[r0-1, base+j] (top boundary, rolling)
#pragma unroll
    for (int j = 0; j < C_COLS; j++) U[j] = INF;
    float lv0 = INF, lv1 = INF, lv2 = INF, lv3 = INF;   // left boundary
    float carry = (t == 0) ? 0.0f : INF;  // d[r0-1, base-1] entering a block

    __syncthreads();

    const float4* sx4 = reinterpret_cast<const float4*>(sx);

    // Prologue: X tiles for superstep 0 (wrap-indexed; garbage is harmless:
    // INF is a fixed point of the recurrence for fill; drain garbage flows
    // only to post-capture state).
    float4 X[SUPER];
#pragma unroll
    for (int u = 0; u < SUPER; u++)
        X[u] = sx4[(0 - sigma + u) & (N_BLK - 1)];

    for (int sup = 0; sup < NSUPER; sup++) {
        const int b0 = sup * SUPER - sigma;

#pragma unroll
        for (int u = 0; u < SUPER; u++) {
            const int s = sup * SUPER + u;
            const int b = b0 + u;
            const float4 xv = X[u];

            // seam consumer pre-load (independent of the tile)
            const float4 rv = ring[rdrow][(s - SKEW_W) & (RING - 1)];

            // ---- 4x8 tile, column-major ----
            float pc0 = lv0, pc1 = lv1, pc2 = lv2, pc3 = lv3;
            float uleft = carry;              // old U[j-1]
#pragma unroll
            for (int j = 0; j < C_COLS; j++) {
                const float Uj = U[j];
                const float c0 = fabsf(xv.x - y[j]) + fminf(fminf(Uj,  uleft), pc0);
                const float c1 = fabsf(xv.y - y[j]) + fminf(fminf(pc1, pc0), c0);
                const float c2 = fabsf(xv.z - y[j]) + fminf(fminf(pc2, pc1), c1);
                const float c3 = fabsf(xv.w - y[j]) + fminf(fminf(pc3, pc2), c2);
                U[j]  = c3;                   // new top boundary for next block
                uleft = Uj;
                pc0 = c0; pc1 = c1; pc2 = c2; pc3 = c3;
            }

            // capture this thread's slice of the boundary row (once)
            if (b == N_BLK - 1) {
                sF4[2 * t]     = make_float4(U[0], U[1], U[2], U[3]);
                sF4[2 * t + 1] = make_float4(U[4], U[5], U[6], U[7]);
            }

            carry = lv3;

            // intra-warp handoff for next step
            const float n0 = __shfl_up_sync(0xffffffffu, pc0, 1);
            const float n1 = __shfl_up_sync(0xffffffffu, pc1, 1);
            const float n2 = __shfl_up_sync(0xffffffffu, pc2, 1);
            const float n3 = __shfl_up_sync(0xffffffffu, pc3, 1);

            // seam producer: single predicated wide store
            if (lane == 31 && warp < 3)
                ring[warp][s & (RING - 1)] = make_float4(pc0, pc1, pc2, pc3);

            // seam consumer select (no branch)
            const bool l0 = (lane == 0);
            lv0 = l0 ? rv.x : n0;
            lv1 = l0 ? rv.y : n1;
            lv2 = l0 ? rv.z : n2;
            lv3 = l0 ? rv.w : n3;
        }

        // software-pipelined X reload for superstep sup+1 (sx is immutable)
        {
            const int b0n = (sup + 1) * SUPER - sigma;
#pragma unroll
            for (int u = 0; u < SUPER; u++)
                X[u] = sx4[(b0n + u) & (N_BLK - 1)];
        }
        __syncthreads();
    }

    // ---- publish boundary row to global ----
    {
        const float4 a  = sF4[2 * t];
        const float4 b4 = sF4[2 * t + 1];
        if (half == 0) {
            float4* gF4 = reinterpret_cast<float4*>(&g_F[pair][0]);
            gF4[2 * t]     = a;
            gF4[2 * t + 1] = b4;
        } else {
            // local col cc maps to original col 1023-cc
            float4* gB4 = reinterpret_cast<float4*>(&g_B[pair][0]);
            gB4[255 - 2 * t] = make_float4(a.w, a.z, a.y, a.x);   // B[1020-8t..1023-8t]
            gB4[254 - 2 * t] = make_float4(b4.w, b4.z, b4.y, b4.x);
        }
    }
    __threadfence();
    if (t == 0) s_sec = atomicInc(&g_pcount[pair], 1);   // 0=first, 1=second
    __syncthreads();

    // ---- second arriver of the pair does the combine ----
    if (s_sec == 1) {
        __threadfence();
        const float4* gF4 = reinterpret_cast<const float4*>(&g_F[pair][0]);
        const float4* gB4 = reinterpret_cast<const float4*>(&g_B[pair][0]);
        const float4 Fa = gF4[2 * t], Fb = gF4[2 * t + 1];
        const float4 Ba = gB4[2 * t], Bb = gB4[2 * t + 1];
        const float  Bn = (t < P_THR - 1) ? g_B[pair][8 * t + 8] : INF;

        float mn =          Fa.x + fminf(Ba.x, Ba.y);
        mn = fminf(mn, Fa.y + fminf(Ba.y, Ba.z));
        mn = fminf(mn, Fa.z + fminf(Ba.z, Ba.w));
        mn = fminf(mn, Fa.w + fminf(Ba.w, Bb.x));
        mn = fminf(mn, Fb.x + fminf(Bb.x, Bb.y));
        mn = fminf(mn, Fb.y + fminf(Bb.y, Bb.z));
        mn = fminf(mn, Fb.z + fminf(Bb.z, Bb.w));
        mn = fminf(mn, Fb.w + fminf(Bb.w, Bn));
#pragma unroll
        for (int o = 16; o; o >>= 1)
            mn = fminf(mn, __shfl_xor_sync(0xffffffffu, mn, o));
        if (lane == 0) sRed[warp] = mn;
        __syncthreads();
        if (t == 0)
            g_dists[pair] = fminf(fminf(sRed[0], sRed[1]),
                                  fminf(sRed[2], sRed[3]));
    }

    // ---- fused epilogue: last of all 128 CTAs does softmax + A @ V ----
    __threadfence();
    if (t == 0) s_last = atomicInc(&g_count, N_CTA - 1);
    __syncthreads();
    if (s_last != N_CTA - 1) return;
    __threadfence();

    if (t < N_SEG) {
        float l[N_SEG];
        float m = -INF;
#pragma unroll
        for (int j = 0; j < N_SEG; j++) {
            l[j] = 0.5f * g_dists[t * N_SEG + j];    // scale = 1/sqrt(4)
            m = fmaxf(m, l[j]);
        }
        float ssum = 0.0f;
#pragma unroll
        for (int j = 0; j < N_SEG; j++) {
            l[j] = expf(l[j] - m);
            ssum += l[j];
        }
        const float inv = 1.0f / ssum;
#pragma unroll
        for (int j = 0; j < N_SEG; j++) sA[t][j] = l[j] * inv;
    }
    __syncthreads();

    const float4* v4 = reinterpret_cast<const float4*>(values);
    float4* o4 = reinterpret_cast<float4*>(out_g);
#pragma unroll
    for (int n = 0; n < 16; n++) {
        const int g = t + n * P_THR;                 // float4 index (2048 total)
        const int i = g >> 8;                        // segment (256 float4/seg)
        const int c = g & 255;
        float4 acc = make_float4(0.f, 0.f, 0.f, 0.f);
#pragma unroll
        for (int j = 0; j < N_SEG; j++) {
            const float w = sA[i][j];
            const float4 v = v4[j * 256 + c];
            acc.x += w * v.x;
            acc.y += w * v.y;
            acc.z += w * v.z;
            acc.w += w * v.w;
        }
        o4[g] = acc;
    }
}

extern "C" void kernel_launch(void* const* d_in, const int* in_sizes, int n_in,
                              void* d_out, int out_size) {
    const float* queries = (const float*)d_in[0];
    const float* keys    = (const float*)d_in[1];
    const float* values  = (const float*)d_in[2];
    float* out = (float*)d_out;

    dim3 grid(N_SEG, N_SEG, 2);
    dtw_kernel<<<grid, P_THR>>>(queries, keys, values, out);
}

// round 14
// speedup vs baseline: 2.6136x; 1.0416x over previous
#include <cuda_runtime.h>
#include <math_constants.h>

// queries/keys/values: 8192 fp32 each; 8 segments of 1024 contiguous floats.
// dists[i][j] = exact DTW(|a-b|) between q-seg i and k-seg j (1024x1024 DP).
// A = softmax(0.5*dists, axis=-1); out = A @ value-segments.
//
// BIDIRECTIONAL SPLIT: every monotone DTW path crosses row 511 -> 512 on one
// down/diag edge, so D = min_j [ F[j] + min(B[j], B[j+1]) ] with
// F[j] = Dfwd(511,j) and B[j] = Dbwd(512,j) (both cost-inclusive).
// CTA (qi,kj,0) computes F via forward DTW on rows 0..511; CTA (qi,kj,1)
// computes B by running the SAME kernel on reversed x rows and reversed y
// cols (Dbwd(i,j) = Dfwd_rev(1023-i,1023-j)), storing its final row
// index-reversed. The second partner to arrive (per-pair atomicInc, no
// spinning) does the 1024-wide combine min-reduction.
// Boundary capture uses explicitly predicated st.shared (inline asm) so the
// per-step capture costs ~3 issue slots instead of a BSSY/BSYNC branch.

#define N_SEG    8
#define SEG_LEN  1024
#define HALF_R   512                          // rows per direction
#define C_COLS   8                            // columns per thread
#define R_ROWS   4                            // rows per pipeline step
#define P_THR    128
#define N_BLK    (HALF_R / R_ROWS)            // 128 row-blocks
#define SKEW_W   8                            // extra skew per warp seam
#define SIG_MAX  (P_THR - 1 + SKEW_W * 3)     // 151
#define N_STEPS  (N_BLK + SIG_MAX)            // 279
#define SUPER    8                            // steps per __syncthreads
#define NSUPER   ((N_STEPS + SUPER - 1) / SUPER)   // 35 -> 280 executed steps
#define RING     16
#define N_CTA    (N_SEG * N_SEG * 2)          // 128

__device__ float        g_dists[N_SEG * N_SEG];
__device__ unsigned int g_count = 0;                  // wraps -> self-reset
__device__ unsigned int g_pcount[N_SEG * N_SEG];      // per-pair, wraps at 1
__device__ float        g_F[N_SEG * N_SEG][SEG_LEN];  // Dfwd(511, j)
__device__ float        g_B[N_SEG * N_SEG][SEG_LEN];  // Dbwd(512, j)

// Predicated STS.128: no branch, predicated-off costs 1 issue slot.
__device__ __forceinline__ void sts128_if(int pred, unsigned addr,
                                          float a, float b, float c, float d) {
    asm volatile(
        "{\n\t"
        ".reg .pred p;\n\t"
        "setp.ne.s32 p, %0, 0;\n\t"
        "@p st.shared.v4.f32 [%1], {%2, %3, %4, %5};\n\t"
        "}"
        :: "r"(pred), "r"(addr), "f"(a), "f"(b), "f"(c), "f"(d) : "memory");
}

__global__ __launch_bounds__(P_THR, 1)
void dtw_kernel(const float* __restrict__ q, const float* __restrict__ k,
                const float* __restrict__ values, float* __restrict__ out_g) {
    const int qi   = blockIdx.x;
    const int kj   = blockIdx.y;
    const int half = blockIdx.z;              // 0 = forward, 1 = backward
    const int pair = qi * N_SEG + kj;
    const float* __restrict__ xrow = q + qi * SEG_LEN;
    const float* __restrict__ ycol = k + kj * SEG_LEN;

    __shared__ float  sx[HALF_R];
    __shared__ float4 ring[4][RING];          // row 3: permanent INF row
    __shared__ float4 sF4[2 * P_THR];         // captured boundary row (1024 f)
    __shared__ float  sA[N_SEG][N_SEG];
    __shared__ float  sRed[4];
    __shared__ unsigned s_sec, s_last;

    const int t    = threadIdx.x;
    const int lane = t & 31;
    const int warp = t >> 5;
    const int sigma = t + SKEW_W * warp;
    const int rdrow = (warp + 3) & 3;         // warp-1; warp0 -> 3 (INF row)
    const float INF = CUDART_INF_F;

    const unsigned sf_addr0 =
        (unsigned)__cvta_generic_to_shared(&sF4[2 * t]);
    const unsigned sf_addr1 = sf_addr0 + 16;

    // x rows for this direction (bwd: reversed rows 1023..512)
    {
        const float4* xr4 = reinterpret_cast<const float4*>(xrow);
        float4* sxd = reinterpret_cast<float4*>(sx);
        if (half == 0) {
            sxd[t] = xr4[t];                          // rows 0..511
        } else {
            const float4 v = xr4[255 - t];            // rows 1023..512 reversed
            sxd[t] = make_float4(v.w, v.z, v.y, v.x);
        }
    }
    {
        const float4 inf4 = make_float4(INF, INF, INF, INF);
        float4* rp = &ring[0][0];
        for (int i = t; i < 4 * RING; i += P_THR) rp[i] = inf4;
    }

    // y columns (bwd: reversed)
    float y[C_COLS];
    {
        const float4* kc4 = reinterpret_cast<const float4*>(ycol);
        if (half == 0) {
            const float4 a = kc4[2 * t], b = kc4[2 * t + 1];
            y[0]=a.x; y[1]=a.y; y[2]=a.z; y[3]=a.w;
            y[4]=b.x; y[5]=b.y; y[6]=b.z; y[7]=b.w;
        } else {
            const float4 a = kc4[255 - 2 * t], b = kc4[254 - 2 * t];
            y[0]=a.w; y[1]=a.z; y[2]=a.y; y[3]=a.x;
            y[4]=b.w; y[5]=b.z; y[6]=b.y; y[7]=b.x;
        }
    }

    float U[C_COLS];                  // d[r0-1, base+j] (top boundary, rolling)
#pragma unroll
    for (int j = 0; j < C_COLS; j++) U[j] = INF;
    float lv0 = INF, lv1 = INF, lv2 = INF, lv3 = INF;   // left boundary
    float carry = (t == 0) ? 0.0f : INF;  // d[r0-1, base-1] entering a block

    __syncthreads();

    const float4* sx4 = reinterpret_cast<const float4*>(sx);

    // Prologue: X tiles for superstep 0 (wrap-indexed; garbage is harmless:
    // INF is a fixed point of the recurrence for fill; drain garbage flows
    // only to post-capture state).
    float4 X[SUPER];
#pragma unroll
    for (int u = 0; u < SUPER; u++)
        X[u] = sx4[(0 - sigma + u) & (N_BLK - 1)];

    for (int sup = 0; sup < NSUPER; sup++) {
        const int b0 = sup * SUPER - sigma;

#pragma unroll
        for (int u = 0; u < SUPER; u++) {
            const int s = sup * SUPER + u;
            const int b = b0 + u;
            const float4 xv = X[u];

            // seam consumer pre-load (independent of the tile)
            const float4 rv = ring[rdrow][(s - SKEW_W) & (RING - 1)];

            // ---- 4x8 tile, column-major ----
            float pc0 = lv0, pc1 = lv1, pc2 = lv2, pc3 = lv3;
            float uleft = carry;              // old U[j-1]
#pragma unroll
            for (int j = 0; j < C_COLS; j++) {
                const float Uj = U[j];
                const float c0 = fabsf(xv.x - y[j]) + fminf(fminf(Uj,  uleft), pc0);
                const float c1 = fabsf(xv.y - y[j]) + fminf(fminf(pc1, pc0), c0);
                const float c2 = fabsf(xv.z - y[j]) + fminf(fminf(pc2, pc1), c1);
                const float c3 = fabsf(xv.w - y[j]) + fminf(fminf(pc3, pc2), c2);
                U[j]  = c3;                   // new top boundary for next block
                uleft = Uj;
                pc0 = c0; pc1 = c1; pc2 = c2; pc3 = c3;
            }

            // capture this thread's slice of the boundary row (predicated,
            // no branch; fires exactly once per thread)
            const int cap = (b == N_BLK - 1);
            sts128_if(cap, sf_addr0, U[0], U[1], U[2], U[3]);
            sts128_if(cap, sf_addr1, U[4], U[5], U[6], U[7]);

            carry = lv3;

            // intra-warp handoff for next step
            const float n0 = __shfl_up_sync(0xffffffffu, pc0, 1);
            const float n1 = __shfl_up_sync(0xffffffffu, pc1, 1);
            const float n2 = __shfl_up_sync(0xffffffffu, pc2, 1);
            const float n3 = __shfl_up_sync(0xffffffffu, pc3, 1);

            // seam producer: single predicated wide store
            if (lane == 31 && warp < 3)
                ring[warp][s & (RING - 1)] = make_float4(pc0, pc1, pc2, pc3);

            // seam consumer select (no branch)
            const bool l0 = (lane == 0);
            lv0 = l0 ? rv.x : n0;
            lv1 = l0 ? rv.y : n1;
            lv2 = l0 ? rv.z : n2;
            lv3 = l0 ? rv.w : n3;
        }

        // software-pipelined X reload for superstep sup+1 (sx is immutable)
        {
            const int b0n = (sup + 1) * SUPER - sigma;
#pragma unroll
            for (int u = 0; u < SUPER; u++)
                X[u] = sx4[(b0n + u) & (N_BLK - 1)];
        }
        __syncthreads();
    }

    // ---- publish boundary row to global ----
    {
        const float4 a  = sF4[2 * t];
        const float4 b4 = sF4[2 * t + 1];
        if (half == 0) {
            float4* gF4 = reinterpret_cast<float4*>(&g_F[pair][0]);
            gF4[2 * t]     = a;
            gF4[2 * t + 1] = b4;
        } else {
            // local col cc maps to original col 1023-cc
            float4* gB4 = reinterpret_cast<float4*>(&g_B[pair][0]);
            gB4[255 - 2 * t] = make_float4(a.w, a.z, a.y, a.x);   // B[1020-8t..1023-8t]
            gB4[254 - 2 * t] = make_float4(b4.w, b4.z, b4.y, b4.x);
        }
    }
    __threadfence();
    if (t == 0) s_sec = atomicInc(&g_pcount[pair], 1);   // 0=first, 1=second
    __syncthreads();

    // ---- second arriver of the pair does the combine ----
    if (s_sec == 1) {
        __threadfence();
        const float4* gF4 = reinterpret_cast<const float4*>(&g_F[pair][0]);
        const float4* gB4 = reinterpret_cast<const float4*>(&g_B[pair][0]);
        const float4 Fa = gF4[2 * t], Fb = gF4[2 * t + 1];
        const float4 Ba = gB4[2 * t], Bb = gB4[2 * t + 1];
        const float  Bn = (t < P_THR - 1) ? g_B[pair][8 * t + 8] : INF;

        float mn =          Fa.x + fminf(Ba.x, Ba.y);
        mn = fminf(mn, Fa.y + fminf(Ba.y, Ba.z));
        mn = fminf(mn, Fa.z + fminf(Ba.z, Ba.w));
        mn = fminf(mn, Fa.w + fminf(Ba.w, Bb.x));
        mn = fminf(mn, Fb.x + fminf(Bb.x, Bb.y));
        mn = fminf(mn, Fb.y + fminf(Bb.y, Bb.z));
        mn = fminf(mn, Fb.z + fminf(Bb.z, Bb.w));
        mn = fminf(mn, Fb.w + fminf(Bb.w, Bn));
#pragma unroll
        for (int o = 16; o; o >>= 1)
            mn = fminf(mn, __shfl_xor_sync(0xffffffffu, mn, o));
        if (lane == 0) sRed[warp] = mn;
        __syncthreads();
        if (t == 0)
            g_dists[pair] = fminf(fminf(sRed[0], sRed[1]),
                                  fminf(sRed[2], sRed[3]));
    }

    // ---- fused epilogue: last of all 128 CTAs does softmax + A @ V ----
    __threadfence();
    if (t == 0) s_last = atomicInc(&g_count, N_CTA - 1);
    __syncthreads();
    if (s_last != N_CTA - 1) return;
    __threadfence();

    if (t < N_SEG) {
        float l[N_SEG];
        float m = -INF;
#pragma unroll
        for (int j = 0; j < N_SEG; j++) {
            l[j] = 0.5f * g_dists[t * N_SEG + j];    // scale = 1/sqrt(4)
            m = fmaxf(m, l[j]);
        }
        float ssum = 0.0f;
#pragma unroll
        for (int j = 0; j < N_SEG; j++) {
            l[j] = expf(l[j] - m);
            ssum += l[j];
        }
        const float inv = 1.0f / ssum;
#pragma unroll
        for (int j = 0; j < N_SEG; j++) sA[t][j] = l[j] * inv;
    }
    __syncthreads();

    const float4* v4 = reinterpret_cast<const float4*>(values);
    float4* o4 = reinterpret_cast<float4*>(out_g);
#pragma unroll
    for (int n = 0; n < 16; n++) {
        const int g = t + n * P_THR;                 // float4 index (2048 total)
        const int i = g >> 8;                        // segment (256 float4/seg)
        const int c = g & 255;
        float4 acc = make_float4(0.f, 0.f, 0.f, 0.f);
#pragma unroll
        for (int j = 0; j < N_SEG; j++) {
            const float w = sA[i][j];
            const float4 v = v4[j * 256 + c];
            acc.x += w * v.x;
            acc.y += w * v.y;
            acc.z += w * v.z;
            acc.w += w * v.w;
        }
        o4[g] = acc;
    }
}

extern "C" void kernel_launch(void* const* d_in, const int* in_sizes, int n_in,
                              void* d_out, int out_size) {
    const float* queries = (const float*)d_in[0];
    const float* keys    = (const float*)d_in[1];
    const float* values  = (const float*)d_in[2];
    float* out = (float*)d_out;

    dim3 grid(N_SEG, N_SEG, 2);
    dtw_kernel<<<grid, P_THR>>>(queries, keys, values, out);
}

// round 15
// speedup vs baseline: 2.6326x; 1.0073x over previous
#include <cuda_runtime.h>
#include <math_constants.h>

// queries/keys/values: 8192 fp32 each; 8 segments of 1024 contiguous floats.
// dists[i][j] = exact DTW(|a-b|) between q-seg i and k-seg j (1024x1024 DP).
// A = softmax(0.5*dists, axis=-1); out = A @ value-segments.
//
// BIDIRECTIONAL SPLIT: every monotone DTW path crosses row 511 -> 512 on one
// down/diag edge, so D = min_j [ F[j] + min(B[j], B[j+1]) ] with
// F[j] = Dfwd(511,j) and B[j] = Dbwd(512,j) (both cost-inclusive).
// CTA (qi,kj,0) computes F via forward DTW on rows 0..511; CTA (qi,kj,1)
// computes B by running the SAME kernel on reversed x rows and reversed y
// cols (Dbwd(i,j) = Dfwd_rev(1023-i,1023-j)), storing its final row
// index-reversed. The second partner to arrive (per-pair atomicInc, no
// spinning) does the 1024-wide combine min-reduction.
// Boundary capture: ONE predicated asm block (single setp, two st.shared.v4,
// NO memory clobber) -> ~3 issue slots per step, no branch, and no compiler
// scheduling barrier (sF4 is only read after the final __syncthreads, which
// is itself a full barrier, so ordering is guaranteed without the clobber).

#define N_SEG    8
#define SEG_LEN  1024
#define HALF_R   512                          // rows per direction
#define C_COLS   8                            // columns per thread
#define R_ROWS   4                            // rows per pipeline step
#define P_THR    128
#define N_BLK    (HALF_R / R_ROWS)            // 128 row-blocks
#define SKEW_W   8                            // extra skew per warp seam
#define SIG_MAX  (P_THR - 1 + SKEW_W * 3)     // 151
#define N_STEPS  (N_BLK + SIG_MAX)            // 279
#define SUPER    8                            // steps per __syncthreads
#define NSUPER   ((N_STEPS + SUPER - 1) / SUPER)   // 35 -> 280 executed steps
#define RING     16
#define N_CTA    (N_SEG * N_SEG * 2)          // 128

__device__ float        g_dists[N_SEG * N_SEG];
__device__ unsigned int g_count = 0;                  // wraps -> self-reset
__device__ unsigned int g_pcount[N_SEG * N_SEG];      // per-pair, wraps at 1
__device__ float        g_F[N_SEG * N_SEG][SEG_LEN];  // Dfwd(511, j)
__device__ float        g_B[N_SEG * N_SEG][SEG_LEN];  // Dbwd(512, j)

// Predicated double STS.128, single setp, NO memory clobber (see header note).
__device__ __forceinline__ void cap_sts(int pred, unsigned addr,
                                        float a, float b, float c, float d,
                                        float e, float f, float g, float h) {
    asm volatile(
        "{\n\t"
        ".reg .pred p;\n\t"
        "setp.ne.s32 p, %0, 0;\n\t"
        "@p st.shared.v4.f32 [%1], {%2, %3, %4, %5};\n\t"
        "@p st.shared.v4.f32 [%1+16], {%6, %7, %8, %9};\n\t"
        "}"
        :: "r"(pred), "r"(addr),
           "f"(a), "f"(b), "f"(c), "f"(d),
           "f"(e), "f"(f), "f"(g), "f"(h));
}

__global__ __launch_bounds__(P_THR, 1)
void dtw_kernel(const float* __restrict__ q, const float* __restrict__ k,
                const float* __restrict__ values, float* __restrict__ out_g) {
    const int qi   = blockIdx.x;
    const int kj   = blockIdx.y;
    const int half = blockIdx.z;              // 0 = forward, 1 = backward
    const int pair = qi * N_SEG + kj;
    const float* __restrict__ xrow = q + qi * SEG_LEN;
    const float* __restrict__ ycol = k + kj * SEG_LEN;

    __shared__ float  sx[HALF_R];
    __shared__ float4 ring[4][RING];          // row 3: permanent INF row
    __shared__ float4 sF4[2 * P_THR];         // captured boundary row (1024 f)
    __shared__ float  sA[N_SEG][N_SEG];
    __shared__ float  sRed[4];
    __shared__ unsigned s_sec, s_last;

    const int t    = threadIdx.x;
    const int lane = t & 31;
    const int warp = t >> 5;
    const int sigma = t + SKEW_W * warp;
    const int rdrow = (warp + 3) & 3;         // warp-1; warp0 -> 3 (INF row)
    const float INF = CUDART_INF_F;

    const unsigned sf_addr =
        (unsigned)__cvta_generic_to_shared(&sF4[2 * t]);

    // x rows for this direction (bwd: reversed rows 1023..512)
    {
        const float4* xr4 = reinterpret_cast<const float4*>(xrow);
        float4* sxd = reinterpret_cast<float4*>(sx);
        if (half == 0) {
            sxd[t] = xr4[t];                          // rows 0..511
        } else {
            const float4 v = xr4[255 - t];            // rows 1023..512 reversed
            sxd[t] = make_float4(v.w, v.z, v.y, v.x);
        }
    }
    {
        const float4 inf4 = make_float4(INF, INF, INF, INF);
        float4* rp = &ring[0][0];
        for (int i = t; i < 4 * RING; i += P_THR) rp[i] = inf4;
    }

    // y columns (bwd: reversed)
    float y[C_COLS];
    {
        const float4* kc4 = reinterpret_cast<const float4*>(ycol);
        if (half == 0) {
            const float4 a = kc4[2 * t], b = kc4[2 * t + 1];
            y[0]=a.x; y[1]=a.y; y[2]=a.z; y[3]=a.w;
            y[4]=b.x; y[5]=b.y; y[6]=b.z; y[7]=b.w;
        } else {
            const float4 a = kc4[255 - 2 * t], b = kc4[254 - 2 * t];
            y[0]=a.w; y[1]=a.z; y[2]=a.y; y[3]=a.x;
            y[4]=b.w; y[5]=b.z; y[6]=b.y; y[7]=b.x;
        }
    }

    float U[C_COLS];                  // d[r0-1, base+j] (top boundary, rolling)
#pragma unroll
    for (int j = 0; j < C_COLS; j++) U[j] = INF;
    float lv0 = INF, lv1 = INF, lv2 = INF, lv3 = INF;   // left boundary
    float carry = (t == 0) ? 0.0f : INF;  // d[r0-1, base-1] entering a block

    __syncthreads();

    const float4* sx4 = reinterpret_cast<const float4*>(sx);

    // Prologue: X tiles for superstep 0 (wrap-indexed; garbage is harmless:
    // INF is a fixed point of the recurrence for fill; drain garbage flows
    // only to post-capture state).
    float4 X[SUPER];
#pragma unroll
    for (int u = 0; u < SUPER; u++)
        X[u] = sx4[(0 - sigma + u) & (N_BLK - 1)];

    for (int sup = 0; sup < NSUPER; sup++) {
        const int b0 = sup * SUPER - sigma;

#pragma unroll
        for (int u = 0; u < SUPER; u++) {
            const int s = sup * SUPER + u;
            const int b = b0 + u;
            const float4 xv = X[u];

            // seam consumer pre-load (independent of the tile)
            const float4 rv = ring[rdrow][(s - SKEW_W) & (RING - 1)];

            // ---- 4x8 tile, column-major ----
            float pc0 = lv0, pc1 = lv1, pc2 = lv2, pc3 = lv3;
            float uleft = carry;              // old U[j-1]
#pragma unroll
            for (int j = 0; j < C_COLS; j++) {
                const float Uj = U[j];
                const float c0 = fabsf(xv.x - y[j]) + fminf(fminf(Uj,  uleft), pc0);
                const float c1 = fabsf(xv.y - y[j]) + fminf(fminf(pc1, pc0), c0);
                const float c2 = fabsf(xv.z - y[j]) + fminf(fminf(pc2, pc1), c1);
                const float c3 = fabsf(xv.w - y[j]) + fminf(fminf(pc3, pc2), c2);
                U[j]  = c3;                   // new top boundary for next block
                uleft = Uj;
                pc0 = c0; pc1 = c1; pc2 = c2; pc3 = c3;
            }

            // capture this thread's slice of the boundary row (predicated,
            // one setp, no branch, no compiler barrier; fires once per thread)
            cap_sts(b == N_BLK - 1, sf_addr,
                    U[0], U[1], U[2], U[3], U[4], U[5], U[6], U[7]);

            carry = lv3;

            // intra-warp handoff for next step
            const float n0 = __shfl_up_sync(0xffffffffu, pc0, 1);
            const float n1 = __shfl_up_sync(0xffffffffu, pc1, 1);
            const float n2 = __shfl_up_sync(0xffffffffu, pc2, 1);
            const float n3 = __shfl_up_sync(0xffffffffu, pc3, 1);

            // seam producer: single predicated wide store
            if (lane == 31 && warp < 3)
                ring[warp][s & (RING - 1)] = make_float4(pc0, pc1, pc2, pc3);

            // seam consumer select (no branch)
            const bool l0 = (lane == 0);
            lv0 = l0 ? rv.x : n0;
            lv1 = l0 ? rv.y : n1;
            lv2 = l0 ? rv.z : n2;
            lv3 = l0 ? rv.w : n3;
        }

        // software-pipelined X reload for superstep sup+1 (sx is immutable)
        {
            const int b0n = (sup + 1) * SUPER - sigma;
#pragma unroll
            for (int u = 0; u < SUPER; u++)
                X[u] = sx4[(b0n + u) & (N_BLK - 1)];
        }
        __syncthreads();
    }

    // ---- publish boundary row to global ----
    {
        const float4 a  = sF4[2 * t];
        const float4 b4 = sF4[2 * t + 1];
        if (half == 0) {
            float4* gF4 = reinterpret_cast<float4*>(&g_F[pair][0]);
            gF4[2 * t]     = a;
            gF4[2 * t + 1] = b4;
        } else {
            // local col cc maps to original col 1023-cc
            float4* gB4 = reinterpret_cast<float4*>(&g_B[pair][0]);
            gB4[255 - 2 * t] = make_float4(a.w, a.z, a.y, a.x);   // B[1020-8t..1023-8t]
            gB4[254 - 2 * t] = make_float4(b4.w, b4.z, b4.y, b4.x);
        }
    }
    __threadfence();
    if (t == 0) s_sec = atomicInc(&g_pcount[pair], 1);   // 0=first, 1=second
    __syncthreads();

    // ---- second arriver of the pair does the combine ----
    if (s_sec == 1) {
        __threadfence();
        const float4* gF4 = reinterpret_cast<const float4*>(&g_F[pair][0]);
        const float4* gB4 = reinterpret_cast<const float4*>(&g_B[pair][0]);
        const float4 Fa = gF4[2 * t], Fb = gF4[2 * t + 1];
        const float4 Ba = gB4[2 * t], Bb = gB4[2 * t + 1];
        const float  Bn = (t < P_THR - 1) ? g_B[pair][8 * t + 8] : INF;

        float mn =          Fa.x + fminf(Ba.x, Ba.y);
        mn = fminf(mn, Fa.y + fminf(Ba.y, Ba.z));
        mn = fminf(mn, Fa.z + fminf(Ba.z, Ba.w));
        mn = fminf(mn, Fa.w + fminf(Ba.w, Bb.x));
        mn = fminf(mn, Fb.x + fminf(Bb.x, Bb.y));
        mn = fminf(mn, Fb.y + fminf(Bb.y, Bb.z));
        mn = fminf(mn, Fb.z + fminf(Bb.z, Bb.w));
        mn = fminf(mn, Fb.w + fminf(Bb.w, Bn));
#pragma unroll
        for (int o = 16; o; o >>= 1)
            mn = fminf(mn, __shfl_xor_sync(0xffffffffu, mn, o));
        if (lane == 0) sRed[warp] = mn;
        __syncthreads();
        if (t == 0)
            g_dists[pair] = fminf(fminf(sRed[0], sRed[1]),
                                  fminf(sRed[2], sRed[3]));
    }

    // ---- fused epilogue: last of all 128 CTAs does softmax + A @ V ----
    __threadfence();
    if (t == 0) s_last = atomicInc(&g_count, N_CTA - 1);
    __syncthreads();
    if (s_last != N_CTA - 1) return;
    __threadfence();

    if (t < N_SEG) {
        float l[N_SEG];
        float m = -INF;
#pragma unroll
        for (int j = 0; j < N_SEG; j++) {
            l[j] = 0.5f * g_dists[t * N_SEG + j];    // scale = 1/sqrt(4)
            m = fmaxf(m, l[j]);
        }
        float ssum = 0.0f;
#pragma unroll
        for (int j = 0; j < N_SEG; j++) {
            l[j] = expf(l[j] - m);
            ssum += l[j];
        }
        const float inv = 1.0f / ssum;
#pragma unroll
        for (int j = 0; j < N_SEG; j++) sA[t][j] = l[j] * inv;
    }
    __syncthreads();

    const float4* v4 = reinterpret_cast<const float4*>(values);
    float4* o4 = reinterpret_cast<float4*>(out_g);
#pragma unroll
    for (int n = 0; n < 16; n++) {
        const int g = t + n * P_THR;                 // float4 index (2048 total)
        const int i = g >> 8;                        // segment (256 float4/seg)
        const int c = g & 255;
        float4 acc = make_float4(0.f, 0.f, 0.f, 0.f);
#pragma unroll
        for (int j = 0; j < N_SEG; j++) {
            const float w = sA[i][j];
            const float4 v = v4[j * 256 + c];
            acc.x += w * v.x;
            acc.y += w * v.y;
            acc.z += w * v.z;
            acc.w += w * v.w;
        }
        o4[g] = acc;
    }
}

extern "C" void kernel_launch(void* const* d_in, const int* in_sizes, int n_in,
                              void* d_out, int out_size) {
    const float* queries = (const float*)d_in[0];
    const float* keys    = (const float*)d_in[1];
    const float* values  = (const float*)d_in[2];
    float* out = (float*)d_out;

    dim3 grid(N_SEG, N_SEG, 2);
    dtw_kernel<<<grid, P_THR>>>(queries, keys, values, out);
}